// round 8
// baseline (speedup 1.0000x reference)
#include <cuda_runtime.h>
#include <cuda_bf16.h>
#include <cuda_fp8.h>
#include <cstdint>

// Problem constants (fixed by setup_inputs)
#define NE   8
#define DOUT 2048
#define DIN  2048
#define SEQ  8192
#define GRP  128
#define KBLK (DIN / GRP)    // 16 K-blocks
#define NBLK (DOUT / GRP)   // 16 N-blocks

// Scratch: quantized values stored as raw e4m3 bytes + fp32 scales.
__device__ __align__(16) uint8_t g_xq[SEQ * DIN];              // 16 MB
__device__ __align__(16) float   g_xs[SEQ * KBLK];             // 512 KB
__device__ __align__(16) uint8_t g_wq[NE * DOUT * DIN];        // 32 MB
__device__ __align__(16) float   g_ws[NE * NBLK * KBLK];       // 8 KB

// fp8 e4m3 quantize: clip+RN == RN-satfinite convert of v/scale
__device__ __forceinline__ uint32_t quant4_e4m3(float4 v, float scale) {
    float4 c = make_float4(v.x / scale, v.y / scale, v.z / scale, v.w / scale);
    __nv_fp8x4_e4m3 q(c);   // RN, satfinite (== clip to +-448 then RN)
    return *reinterpret_cast<uint32_t*>(&q);
}

// ---------------------------------------------------------------------------
// Fused quant kernel: blocks [0,2048) do weight blocks, [2048,10240) do
// activation tiles. The two phases are independent and both HBM-bound, so
// overlapping them raises achieved bandwidth.
// ---------------------------------------------------------------------------
#define QW_BLOCKS (NE * NBLK * KBLK)          // 2048
#define QX_BLOCKS (SEQ * KBLK / 16)           // 8192

__global__ __launch_bounds__(256) void quant_all_kernel(const float* __restrict__ x,
                                                        const float* __restrict__ w) {
    if (blockIdx.x < QW_BLOCKS) {
        // ---- per 128x128 weight block quant ----
        int b   = blockIdx.x;
        int e   = b >> 8;
        int rem = b & 255;
        int nb  = rem >> 4;
        int kb  = rem & 15;

        const size_t base = ((size_t)(e * DOUT + nb * GRP)) * DIN + kb * GRP;
        const float* src = w + base;
        uint8_t* dst = g_wq + base;

        int tid  = threadIdx.x;
        int lane = tid & 31;
        int warp = tid >> 5;

        float a = 0.0f;
#pragma unroll
        for (int i = tid; i < 4096; i += 256) {
            int r = i >> 5, c = i & 31;
            float4 v = *reinterpret_cast<const float4*>(src + (size_t)r * DIN + c * 4);
            a = fmaxf(a, fmaxf(fmaxf(fabsf(v.x), fabsf(v.y)), fmaxf(fabsf(v.z), fabsf(v.w))));
        }
#pragma unroll
        for (int o = 16; o; o >>= 1) a = fmaxf(a, __shfl_xor_sync(0xffffffffu, a, o));

        __shared__ float red[8];
        __shared__ float s_scale;
        if (lane == 0) red[warp] = a;
        __syncthreads();
        if (tid == 0) {
            float m = red[0];
#pragma unroll
            for (int i = 1; i < 8; i++) m = fmaxf(m, red[i]);
            s_scale = fmaxf(m, 1e-12f) / 448.0f;
        }
        __syncthreads();
        float scale = s_scale;

#pragma unroll
        for (int i = tid; i < 4096; i += 256) {
            int r = i >> 5, c = i & 31;
            float4 v = *reinterpret_cast<const float4*>(src + (size_t)r * DIN + c * 4);
            *reinterpret_cast<uint32_t*>(dst + (size_t)r * DIN + c * 4) = quant4_e4m3(v, scale);
        }
        if (tid == 0) g_ws[(e * NBLK + nb) * KBLK + kb] = scale;
    } else {
        // ---- per 1x128 activation tile quant, two tiles per warp ----
        int bx   = blockIdx.x - QW_BLOCKS;
        int warp = threadIdx.x >> 5;
        int lane = threadIdx.x & 31;
        int t0 = (bx * 8 + warp) * 2;

        const float4 v0 = *reinterpret_cast<const float4*>(x + (size_t)t0 * GRP + lane * 4);
        const float4 v1 = *reinterpret_cast<const float4*>(x + (size_t)(t0 + 1) * GRP + lane * 4);

        float a0 = fmaxf(fmaxf(fabsf(v0.x), fabsf(v0.y)), fmaxf(fabsf(v0.z), fabsf(v0.w)));
        float a1 = fmaxf(fmaxf(fabsf(v1.x), fabsf(v1.y)), fmaxf(fabsf(v1.z), fabsf(v1.w)));
#pragma unroll
        for (int o = 16; o; o >>= 1) {
            a0 = fmaxf(a0, __shfl_xor_sync(0xffffffffu, a0, o));
            a1 = fmaxf(a1, __shfl_xor_sync(0xffffffffu, a1, o));
        }
        float s0 = fmaxf(a0, 1e-12f) / 448.0f;
        float s1 = fmaxf(a1, 1e-12f) / 448.0f;

        *reinterpret_cast<uint32_t*>(g_xq + (size_t)t0 * GRP + lane * 4)       = quant4_e4m3(v0, s0);
        *reinterpret_cast<uint32_t*>(g_xq + (size_t)(t0 + 1) * GRP + lane * 4) = quant4_e4m3(v1, s1);
        if (lane == 0) { g_xs[t0] = s0; g_xs[t0 + 1] = s1; }
    }
}

// ---------------------------------------------------------------------------
// GEMM: 128x128 CTA tile, 512 threads / 16 warps, warp tile 32x32,
// BK=128 stages (one scale block), fp8 QMMA, SW128 swizzle, 3-stage cp.async.
// ---------------------------------------------------------------------------
#define BM    128
#define BN    128
#define BKS   128
#define STG   3
#define TILEB 16384               // 128 rows x 128 B
#define STAGEB (2 * TILEB)
#define SMEM_REQ (STG * STAGEB)   // 98304 B
#define NTHREADS 512

__device__ __forceinline__ void cp16(uint32_t dst, const void* src, int src_bytes) {
    asm volatile("cp.async.cg.shared.global [%0], [%1], 16, %2;\n"
                 :: "r"(dst), "l"(src), "r"(src_bytes) : "memory");
}
__device__ __forceinline__ void ldm_x4(uint32_t r[4], uint32_t addr) {
    asm volatile("ldmatrix.sync.aligned.m8n8.x4.shared.b16 {%0,%1,%2,%3}, [%4];"
                 : "=r"(r[0]), "=r"(r[1]), "=r"(r[2]), "=r"(r[3]) : "r"(addr));
}
__device__ __forceinline__ void mma_fp8(float c[4], const uint32_t a[4], const uint32_t b[2]) {
    asm volatile(
        "mma.sync.aligned.m16n8k32.row.col.f32.e4m3.e4m3.f32 "
        "{%0,%1,%2,%3}, {%4,%5,%6,%7}, {%8,%9}, {%0,%1,%2,%3};"
        : "+f"(c[0]), "+f"(c[1]), "+f"(c[2]), "+f"(c[3])
        : "r"(a[0]), "r"(a[1]), "r"(a[2]), "r"(a[3]), "r"(b[0]), "r"(b[1]));
}
__device__ __forceinline__ uint32_t smem_u32(const void* p) {
    uint32_t a;
    asm("{ .reg .u64 t; cvta.to.shared.u64 t, %1; cvt.u32.u64 %0, t; }" : "=r"(a) : "l"(p));
    return a;
}
// SW128 swizzle, 16B-granular: physical = row*128 + (off16 ^ ((row&7)<<4))
__device__ __forceinline__ uint32_t swz(int row, int off) {
    return (uint32_t)(row * 128 + (off ^ ((row & 7) << 4)));
}

__global__ __launch_bounds__(NTHREADS, 1) void gemm_kernel(float* __restrict__ out,
                                                           const int* __restrict__ tpe) {
    extern __shared__ __align__(128) uint8_t sm[];
    const uint32_t s0 = smem_u32(sm);

    const int tid  = threadIdx.x;
    const int lane = tid & 31;
    const int wrp  = tid >> 5;          // 0..15
    const int wm   = wrp & 3;           // 4 warps along M (32 rows each)
    const int wn   = wrp >> 2;          // 4 warps along N (32 cols each)

    const int m0 = blockIdx.y * BM;
    const int n0 = blockIdx.x * BN;

    // Expert lookup (prefix sum over 8 counts)
    int accv = 0, e = -1, rs = 0, re = 0;
#pragma unroll
    for (int i = 0; i < NE; i++) {
        int c = tpe[i];
        if (e < 0 && m0 >= accv && m0 < accv + c) { e = i; rs = accv; re = accv + c; }
        accv += c;
    }
    if (e < 0) { e = 0; rs = 0; re = 0; }   // fully zero tile

    const uint8_t* Aptr = g_xq;
    const uint8_t* Bptr = g_wq + (size_t)e * DOUT * DIN;

    // Stage loader: 1024 A + 1024 B 16B chunks; 4 per thread.
    auto load_stage = [&](int kb, int st) {
        const int kc = kb * BKS;
        const uint32_t ab = s0 + st * STAGEB;
        const uint32_t bb = ab + TILEB;
#pragma unroll
        for (int i = 0; i < 2; i++) {
            int cid = tid + NTHREADS * i;     // 0..1023
            int row = cid >> 3;
            int off = (cid & 7) * 16;
            uint32_t sw = swz(row, off);
            int gr = m0 + row;
            cp16(ab + sw, Aptr + (size_t)gr * DIN + kc + off,
                 (gr >= rs && gr < re) ? 16 : 0);
            cp16(bb + sw, Bptr + (size_t)(n0 + row) * DIN + kc + off, 16);
        }
        asm volatile("cp.async.commit_group;\n" ::: "memory");
    };

    // Fragment loaders (same verified lane mapping, narrower warp tile)
    auto ldA = [&](int st, int ks, uint32_t af[2][4]) {
        const int k0 = ks * 32;
#pragma unroll
        for (int mi = 0; mi < 2; mi++) {
            int row = wm * 32 + mi * 16 + (lane & 15);
            int cb  = k0 + ((lane >> 4) << 4);
            ldm_x4(af[mi], s0 + st * STAGEB + swz(row, cb));
        }
    };
    auto ldB = [&](int st, int ks, uint32_t bf[4][2]) {
        const int k0 = ks * 32;
#pragma unroll
        for (int nj = 0; nj < 2; nj++) {
            int g  = lane >> 3;
            int n  = wn * 32 + nj * 16 + ((g >> 1) << 3) + (lane & 7);
            int kk = k0 + ((g & 1) << 4);
            uint32_t r[4];
            ldm_x4(r, s0 + st * STAGEB + TILEB + swz(n, kk));
            bf[nj * 2 + 0][0] = r[0]; bf[nj * 2 + 0][1] = r[1];
            bf[nj * 2 + 1][0] = r[2]; bf[nj * 2 + 1][1] = r[3];
        }
    };

    float tot[2][4][4];
#pragma unroll
    for (int mi = 0; mi < 2; mi++)
#pragma unroll
        for (int ni = 0; ni < 4; ni++)
#pragma unroll
            for (int q = 0; q < 4; q++) tot[mi][ni][q] = 0.f;

    const int swbase = (e * NBLK + (n0 >> 7)) * KBLK;
    const int ra0 = m0 + wm * 32 + (lane >> 2);

    load_stage(0, 0);
    load_stage(1, 1);

#pragma unroll 1
    for (int kb = 0; kb < KBLK; kb++) {
        const int st = kb % STG;

        asm volatile("cp.async.wait_group 1;\n" ::: "memory");
        __syncthreads();   // stage kb visible; all warps done with stage kb-1

        if (kb + 2 < KBLK) load_stage(kb + 2, (kb + 2) % STG);
        else               asm volatile("cp.async.commit_group;\n" ::: "memory");

        // Per-K-block scales
        const float swv = g_ws[swbase + kb];
        float sx[2][2];
#pragma unroll
        for (int mi = 0; mi < 2; mi++) {
            sx[mi][0] = g_xs[(ra0 + mi * 16) * KBLK + kb] * swv;
            sx[mi][1] = g_xs[(ra0 + mi * 16 + 8) * KBLK + kb] * swv;
        }

        float par[2][4][4];
#pragma unroll
        for (int mi = 0; mi < 2; mi++)
#pragma unroll
            for (int ni = 0; ni < 4; ni++)
#pragma unroll
                for (int q = 0; q < 4; q++) par[mi][ni][q] = 0.f;

        uint32_t af[2][2][4];
        uint32_t bf[2][4][2];
        ldA(st, 0, af[0]);
        ldB(st, 0, bf[0]);

#pragma unroll
        for (int ks = 0; ks < 4; ks++) {
            const int cb = ks & 1;
            if (ks < 3) {
                ldA(st, ks + 1, af[cb ^ 1]);
                ldB(st, ks + 1, bf[cb ^ 1]);
            }
#pragma unroll
            for (int mi = 0; mi < 2; mi++)
#pragma unroll
                for (int ni = 0; ni < 4; ni++)
                    mma_fp8(par[mi][ni], af[cb][mi], bf[cb][ni]);
        }

        // Fold per-K-block scales into fp32 totals
#pragma unroll
        for (int mi = 0; mi < 2; mi++)
#pragma unroll
            for (int ni = 0; ni < 4; ni++) {
                tot[mi][ni][0] = fmaf(par[mi][ni][0], sx[mi][0], tot[mi][ni][0]);
                tot[mi][ni][1] = fmaf(par[mi][ni][1], sx[mi][0], tot[mi][ni][1]);
                tot[mi][ni][2] = fmaf(par[mi][ni][2], sx[mi][1], tot[mi][ni][2]);
                tot[mi][ni][3] = fmaf(par[mi][ni][3], sx[mi][1], tot[mi][ni][3]);
            }
    }

    // Epilogue: fp32 stores; rows outside the expert range get zeros
#pragma unroll
    for (int mi = 0; mi < 2; mi++) {
        int r0 = m0 + wm * 32 + mi * 16 + (lane >> 2);
        int r1 = r0 + 8;
        bool in0 = (r0 >= rs && r0 < re);
        bool in1 = (r1 >= rs && r1 < re);
#pragma unroll
        for (int ni = 0; ni < 4; ni++) {
            int col = n0 + wn * 32 + ni * 8 + ((lane & 3) << 1);
            float2 v0 = {in0 ? tot[mi][ni][0] : 0.f, in0 ? tot[mi][ni][1] : 0.f};
            float2 v1 = {in1 ? tot[mi][ni][2] : 0.f, in1 ? tot[mi][ni][3] : 0.f};
            *reinterpret_cast<float2*>(out + (size_t)r0 * DOUT + col) = v0;
            *reinterpret_cast<float2*>(out + (size_t)r1 * DOUT + col) = v1;
        }
    }
}

// ---------------------------------------------------------------------------
extern "C" void kernel_launch(void* const* d_in, const int* in_sizes, int n_in,
                              void* d_out, int out_size) {
    const float* x   = (const float*)d_in[0];
    const float* w   = (const float*)d_in[1];
    const int*   tpe = (const int*)d_in[2];
    float* out = (float*)d_out;

    cudaFuncSetAttribute(gemm_kernel, cudaFuncAttributeMaxDynamicSharedMemorySize, SMEM_REQ);

    quant_all_kernel<<<QW_BLOCKS + QX_BLOCKS, 256>>>(x, w);
    gemm_kernel<<<dim3(DOUT / BN, SEQ / BM), NTHREADS, SMEM_REQ>>>(out, tpe);
}

// round 9
// speedup vs baseline: 1.0726x; 1.0726x over previous
#include <cuda_runtime.h>
#include <cuda_bf16.h>
#include <cuda_fp8.h>
#include <cstdint>

// Problem constants (fixed by setup_inputs)
#define NE   8
#define DOUT 2048
#define DIN  2048
#define SEQ  8192
#define GRP  128
#define KBLK (DIN / GRP)    // 16 K-blocks
#define NBLK (DOUT / GRP)   // 16 N-blocks

// Scratch: quantized values stored as raw e4m3 bytes + fp32 scales.
__device__ __align__(16) uint8_t g_xq[SEQ * DIN];              // 16 MB
__device__ __align__(16) float   g_xs[SEQ * KBLK];             // 512 KB
__device__ __align__(16) uint8_t g_wq[NE * DOUT * DIN];        // 32 MB
__device__ __align__(16) float   g_ws[NE * NBLK * KBLK];       // 8 KB

// fp8 e4m3 quantize: clip+RN == RN-satfinite convert of v/scale
__device__ __forceinline__ uint32_t quant4_e4m3(float4 v, float scale) {
    float4 c = make_float4(v.x / scale, v.y / scale, v.z / scale, v.w / scale);
    __nv_fp8x4_e4m3 q(c);   // RN, satfinite (== clip to +-448 then RN)
    return *reinterpret_cast<uint32_t*>(&q);
}

// ---------------------------------------------------------------------------
// Fused quant kernel: blocks [0,2048) do weight blocks, [2048,10240) do
// activation tiles. Both phases are HBM-bound; overlapping them raises BW.
// ---------------------------------------------------------------------------
#define QW_BLOCKS (NE * NBLK * KBLK)          // 2048
#define QX_BLOCKS (SEQ * KBLK / 16)           // 8192

__global__ __launch_bounds__(256) void quant_all_kernel(const float* __restrict__ x,
                                                        const float* __restrict__ w) {
    if (blockIdx.x < QW_BLOCKS) {
        // ---- per 128x128 weight block quant ----
        int b   = blockIdx.x;
        int e   = b >> 8;
        int rem = b & 255;
        int nb  = rem >> 4;
        int kb  = rem & 15;

        const size_t base = ((size_t)(e * DOUT + nb * GRP)) * DIN + kb * GRP;
        const float* src = w + base;
        uint8_t* dst = g_wq + base;

        int tid  = threadIdx.x;
        int lane = tid & 31;
        int warp = tid >> 5;

        float a = 0.0f;
#pragma unroll
        for (int i = tid; i < 4096; i += 256) {
            int r = i >> 5, c = i & 31;
            float4 v = *reinterpret_cast<const float4*>(src + (size_t)r * DIN + c * 4);
            a = fmaxf(a, fmaxf(fmaxf(fabsf(v.x), fabsf(v.y)), fmaxf(fabsf(v.z), fabsf(v.w))));
        }
#pragma unroll
        for (int o = 16; o; o >>= 1) a = fmaxf(a, __shfl_xor_sync(0xffffffffu, a, o));

        __shared__ float red[8];
        __shared__ float s_scale;
        if (lane == 0) red[warp] = a;
        __syncthreads();
        if (tid == 0) {
            float m = red[0];
#pragma unroll
            for (int i = 1; i < 8; i++) m = fmaxf(m, red[i]);
            s_scale = fmaxf(m, 1e-12f) / 448.0f;
        }
        __syncthreads();
        float scale = s_scale;

#pragma unroll
        for (int i = tid; i < 4096; i += 256) {
            int r = i >> 5, c = i & 31;
            float4 v = *reinterpret_cast<const float4*>(src + (size_t)r * DIN + c * 4);
            *reinterpret_cast<uint32_t*>(dst + (size_t)r * DIN + c * 4) = quant4_e4m3(v, scale);
        }
        if (tid == 0) g_ws[(e * NBLK + nb) * KBLK + kb] = scale;
    } else {
        // ---- per 1x128 activation tile quant, two tiles per warp ----
        int bx   = blockIdx.x - QW_BLOCKS;
        int warp = threadIdx.x >> 5;
        int lane = threadIdx.x & 31;
        int t0 = (bx * 8 + warp) * 2;

        const float4 v0 = *reinterpret_cast<const float4*>(x + (size_t)t0 * GRP + lane * 4);
        const float4 v1 = *reinterpret_cast<const float4*>(x + (size_t)(t0 + 1) * GRP + lane * 4);

        float a0 = fmaxf(fmaxf(fabsf(v0.x), fabsf(v0.y)), fmaxf(fabsf(v0.z), fabsf(v0.w)));
        float a1 = fmaxf(fmaxf(fabsf(v1.x), fabsf(v1.y)), fmaxf(fabsf(v1.z), fabsf(v1.w)));
#pragma unroll
        for (int o = 16; o; o >>= 1) {
            a0 = fmaxf(a0, __shfl_xor_sync(0xffffffffu, a0, o));
            a1 = fmaxf(a1, __shfl_xor_sync(0xffffffffu, a1, o));
        }
        float s0 = fmaxf(a0, 1e-12f) / 448.0f;
        float s1 = fmaxf(a1, 1e-12f) / 448.0f;

        *reinterpret_cast<uint32_t*>(g_xq + (size_t)t0 * GRP + lane * 4)       = quant4_e4m3(v0, s0);
        *reinterpret_cast<uint32_t*>(g_xq + (size_t)(t0 + 1) * GRP + lane * 4) = quant4_e4m3(v1, s1);
        if (lane == 0) { g_xs[t0] = s0; g_xs[t0 + 1] = s1; }
    }
}

// ---------------------------------------------------------------------------
// GEMM: 128x128 CTA tile, 256 threads / 8 warps (warp tile 32x64),
// BK=128 stages, fp8 QMMA, SW128 swizzle, 3-stage cp.async, 2 CTAs/SM.
// Accumulators kept in units of the current K-block scale (running rescale)
// so the QMMAs accumulate in place -> no `par` registers -> occupancy 2.
// ---------------------------------------------------------------------------
#define BM    128
#define BN    128
#define BKS   128
#define STG   3
#define TILEB 16384               // 128 rows x 128 B
#define STAGEB (2 * TILEB)
#define SMEM_REQ (STG * STAGEB)   // 98304 B -> 2 CTAs/SM (196.6KB of 227KB)

__device__ __forceinline__ void cp16(uint32_t dst, const void* src, int src_bytes) {
    asm volatile("cp.async.cg.shared.global [%0], [%1], 16, %2;\n"
                 :: "r"(dst), "l"(src), "r"(src_bytes) : "memory");
}
__device__ __forceinline__ void ldm_x4(uint32_t r[4], uint32_t addr) {
    asm volatile("ldmatrix.sync.aligned.m8n8.x4.shared.b16 {%0,%1,%2,%3}, [%4];"
                 : "=r"(r[0]), "=r"(r[1]), "=r"(r[2]), "=r"(r[3]) : "r"(addr));
}
__device__ __forceinline__ void mma_fp8(float c[4], const uint32_t a[4], const uint32_t b[2]) {
    asm volatile(
        "mma.sync.aligned.m16n8k32.row.col.f32.e4m3.e4m3.f32 "
        "{%0,%1,%2,%3}, {%4,%5,%6,%7}, {%8,%9}, {%0,%1,%2,%3};"
        : "+f"(c[0]), "+f"(c[1]), "+f"(c[2]), "+f"(c[3])
        : "r"(a[0]), "r"(a[1]), "r"(a[2]), "r"(a[3]), "r"(b[0]), "r"(b[1]));
}
__device__ __forceinline__ uint32_t smem_u32(const void* p) {
    uint32_t a;
    asm("{ .reg .u64 t; cvta.to.shared.u64 t, %1; cvt.u32.u64 %0, t; }" : "=r"(a) : "l"(p));
    return a;
}
// SW128 swizzle, 16B-granular: physical = row*128 + (off16 ^ ((row&7)<<4))
__device__ __forceinline__ uint32_t swz(int row, int off) {
    return (uint32_t)(row * 128 + (off ^ ((row & 7) << 4)));
}

__global__ __launch_bounds__(256, 2) void gemm_kernel(float* __restrict__ out,
                                                      const int* __restrict__ tpe) {
    extern __shared__ __align__(128) uint8_t sm[];
    const uint32_t s0 = smem_u32(sm);

    const int tid  = threadIdx.x;
    const int lane = tid & 31;
    const int wrp  = tid >> 5;          // 0..7
    const int wm   = wrp & 3;           // 4 warps along M (32 rows each)
    const int wn   = wrp >> 2;          // 2 warps along N (64 cols each)

    const int m0 = blockIdx.y * BM;
    const int n0 = blockIdx.x * BN;

    // Expert lookup (prefix sum over 8 counts)
    int accv = 0, e = -1, rs = 0, re = 0;
#pragma unroll
    for (int i = 0; i < NE; i++) {
        int c = tpe[i];
        if (e < 0 && m0 >= accv && m0 < accv + c) { e = i; rs = accv; re = accv + c; }
        accv += c;
    }
    if (e < 0) { e = 0; rs = 0; re = 0; }   // fully zero tile

    const uint8_t* Aptr = g_xq;
    const uint8_t* Bptr = g_wq + (size_t)e * DOUT * DIN;

    // Stage loader: 1024 A + 1024 B 16B chunks; 8 per thread.
    auto load_stage = [&](int kb, int st) {
        const int kc = kb * BKS;
        const uint32_t ab = s0 + st * STAGEB;
        const uint32_t bb = ab + TILEB;
#pragma unroll
        for (int i = 0; i < 4; i++) {
            int cid = tid + 256 * i;          // 0..1023
            int row = cid >> 3;
            int off = (cid & 7) * 16;
            uint32_t sw = swz(row, off);
            int gr = m0 + row;
            cp16(ab + sw, Aptr + (size_t)gr * DIN + kc + off,
                 (gr >= rs && gr < re) ? 16 : 0);
            cp16(bb + sw, Bptr + (size_t)(n0 + row) * DIN + kc + off, 16);
        }
        asm volatile("cp.async.commit_group;\n" ::: "memory");
    };

    // Fragment loaders (lane mapping identical to the verified R5/R7 kernels)
    auto ldA = [&](int st, int ks, uint32_t af[2][4]) {
        const int k0 = ks * 32;
#pragma unroll
        for (int mi = 0; mi < 2; mi++) {
            int row = wm * 32 + mi * 16 + (lane & 15);
            int cb  = k0 + ((lane >> 4) << 4);
            ldm_x4(af[mi], s0 + st * STAGEB + swz(row, cb));
        }
    };
    auto ldB = [&](int st, int ks, uint32_t bf[8][2]) {
        const int k0 = ks * 32;
#pragma unroll
        for (int nj = 0; nj < 4; nj++) {
            int g  = lane >> 3;
            int n  = wn * 64 + nj * 16 + ((g >> 1) << 3) + (lane & 7);
            int kk = k0 + ((g & 1) << 4);
            uint32_t r[4];
            ldm_x4(r, s0 + st * STAGEB + TILEB + swz(n, kk));
            bf[nj * 2 + 0][0] = r[0]; bf[nj * 2 + 0][1] = r[1];
            bf[nj * 2 + 1][0] = r[2]; bf[nj * 2 + 1][1] = r[3];
        }
    };

    float tot[2][8][4];
#pragma unroll
    for (int mi = 0; mi < 2; mi++)
#pragma unroll
        for (int ni = 0; ni < 8; ni++)
#pragma unroll
            for (int q = 0; q < 4; q++) tot[mi][ni][q] = 0.f;

    const int swbase = (e * NBLK + (n0 >> 7)) * KBLK;
    const int ra0 = m0 + wm * 32 + (lane >> 2);
    float sold[2][2];   // running block scale per (mi, row-half)

    load_stage(0, 0);
    load_stage(1, 1);

#pragma unroll 1
    for (int kb = 0; kb < KBLK; kb++) {
        const int st = kb % STG;

        // Prefetch this K-block's scales before the stage wait (independent of smem)
        const float swv = g_ws[swbase + kb];
        float snew[2][2];
#pragma unroll
        for (int mi = 0; mi < 2; mi++) {
            snew[mi][0] = g_xs[(ra0 + mi * 16) * KBLK + kb] * swv;
            snew[mi][1] = g_xs[(ra0 + mi * 16 + 8) * KBLK + kb] * swv;
        }

        asm volatile("cp.async.wait_group 1;\n" ::: "memory");
        __syncthreads();   // stage kb visible; all warps done with stage kb-1

        if (kb + 2 < KBLK) load_stage(kb + 2, (kb + 2) % STG);
        else               asm volatile("cp.async.commit_group;\n" ::: "memory");

        // Rescale running accumulators into the new block-scale units
        if (kb) {
            float ratio[2][2];
#pragma unroll
            for (int mi = 0; mi < 2; mi++) {
                ratio[mi][0] = sold[mi][0] / snew[mi][0];
                ratio[mi][1] = sold[mi][1] / snew[mi][1];
            }
#pragma unroll
            for (int mi = 0; mi < 2; mi++)
#pragma unroll
                for (int ni = 0; ni < 8; ni++) {
                    tot[mi][ni][0] *= ratio[mi][0];
                    tot[mi][ni][1] *= ratio[mi][0];
                    tot[mi][ni][2] *= ratio[mi][1];
                    tot[mi][ni][3] *= ratio[mi][1];
                }
        }
#pragma unroll
        for (int mi = 0; mi < 2; mi++) { sold[mi][0] = snew[mi][0]; sold[mi][1] = snew[mi][1]; }

        // 4 k-steps, QMMAs accumulate directly into tot
#pragma unroll
        for (int ks = 0; ks < 4; ks++) {
            uint32_t af[2][4];
            uint32_t bf[8][2];
            ldA(st, ks, af);
            ldB(st, ks, bf);
#pragma unroll
            for (int mi = 0; mi < 2; mi++)
#pragma unroll
                for (int ni = 0; ni < 8; ni++)
                    mma_fp8(tot[mi][ni], af[mi], bf[ni]);
        }
    }

    // Epilogue: apply the final block scale; rows outside expert range -> zeros
#pragma unroll
    for (int mi = 0; mi < 2; mi++) {
        int r0 = m0 + wm * 32 + mi * 16 + (lane >> 2);
        int r1 = r0 + 8;
        bool in0 = (r0 >= rs && r0 < re);
        bool in1 = (r1 >= rs && r1 < re);
        float f0 = in0 ? sold[mi][0] : 0.f;
        float f1 = in1 ? sold[mi][1] : 0.f;
#pragma unroll
        for (int ni = 0; ni < 8; ni++) {
            int col = n0 + wn * 64 + ni * 8 + ((lane & 3) << 1);
            float2 v0 = {tot[mi][ni][0] * f0, tot[mi][ni][1] * f0};
            float2 v1 = {tot[mi][ni][2] * f1, tot[mi][ni][3] * f1};
            *reinterpret_cast<float2*>(out + (size_t)r0 * DOUT + col) = v0;
            *reinterpret_cast<float2*>(out + (size_t)r1 * DOUT + col) = v1;
        }
    }
}

// ---------------------------------------------------------------------------
extern "C" void kernel_launch(void* const* d_in, const int* in_sizes, int n_in,
                              void* d_out, int out_size) {
    const float* x   = (const float*)d_in[0];
    const float* w   = (const float*)d_in[1];
    const int*   tpe = (const int*)d_in[2];
    float* out = (float*)d_out;

    cudaFuncSetAttribute(gemm_kernel, cudaFuncAttributeMaxDynamicSharedMemorySize, SMEM_REQ);

    quant_all_kernel<<<QW_BLOCKS + QX_BLOCKS, 256>>>(x, w);
    gemm_kernel<<<dim3(DOUT / BN, SEQ / BM), 256, SMEM_REQ>>>(out, tpe);
}